// round 1
// baseline (speedup 1.0000x reference)
#include <cuda_runtime.h>

// DEQ: z_{t+1} = tanh(x A^T + A_b + B_b + z_t B^T), 10 total applications
// (contraction factor ~0.12 -> converged to ~1e-9), then y = z h^T + h_b.
//
// One CTA = 128 batch rows, fully resident in SMEM. fp32 SIMT GEMM with
// 8x8 register tiles, B^T / z^T / c^T staged in shared memory.

#define D        128      // state dim
#define TM       128      // rows per CTA
#define LDZ      132      // padded row stride (floats), keeps 16B alignment
#define NAPP     10       // total tanh applications
#define THREADS  256

// floats of dynamic smem: W(D*LDZ) + ZT(D*LDZ) + CT(D*LDZ) + hs(D) + aw(4D) + ab(D)
#define SMEM_FLOATS (3 * D * LDZ + D + 4 * D + D)
#define SMEM_BYTES  (SMEM_FLOATS * 4)

// Exact tanh via exp identity; uses fast EX2-based exp. Accurate to ~1e-7 abs
// for all inputs (including +-inf saturation), independent of -use_fast_math.
__device__ __forceinline__ float tanh_fast(float v) {
    float e = __expf(2.0f * v);
    return 1.0f - __fdividef(2.0f, e + 1.0f);
}

__global__ void __launch_bounds__(THREADS, 1)
deq_kernel(const float* __restrict__ x,
           const float* __restrict__ Aw,
           const float* __restrict__ Ab,
           const float* __restrict__ Bw,
           const float* __restrict__ Bb,
           const float* __restrict__ hw,
           const float* __restrict__ hb,
           float* __restrict__ out)
{
    extern __shared__ float sm[];
    float* W  = sm;                  // W[j*LDZ + i] = Bw[i*D + j]   (B^T)
    float* ZT = W  + D * LDZ;        // ZT[i*LDZ + r] = z[r][i]      (z^T)
    float* CT = ZT + D * LDZ;        // CT[i*LDZ + r] = c[r][i]      (c^T)
    float* hs = CT + D * LDZ;        // h weights [D]
    float* aw = hs + D;              // A_w staged [D*4]
    float* ab = aw + D * 4;          // A_b + B_b  [D]

    const int tid  = threadIdx.x;
    const int row0 = blockIdx.x * TM;

    // ---- stage parameters ----
    for (int i = tid; i < D; i += THREADS) {
        hs[i] = hw[i];
        ab[i] = Ab[i] + Bb[i];
    }
    for (int i = tid; i < D * 4; i += THREADS) aw[i] = Aw[i];
    // transpose B into SMEM (coalesced global reads)
    for (int idx = tid; idx < D * D; idx += THREADS) {
        int i = idx >> 7;          // output-state index
        int j = idx & (D - 1);     // input-state index
        W[j * LDZ + i] = Bw[idx];
    }
    __syncthreads();

    // ---- c = x A^T + (A_b + B_b), z1 = tanh(c) ----
    const float4* x4 = (const float4*)x;
    for (int idx = tid; idx < D * TM; idx += THREADS) {
        int i = idx >> 7;          // state index
        int r = idx & (TM - 1);    // row within tile
        float4 xv = x4[row0 + r];
        float c = ab[i]
                + xv.x * aw[i * 4 + 0]
                + xv.y * aw[i * 4 + 1]
                + xv.z * aw[i * 4 + 2]
                + xv.w * aw[i * 4 + 3];
        CT[i * LDZ + r] = c;
        ZT[i * LDZ + r] = tanh_fast(c);
    }
    __syncthreads();

    // ---- fixed-point iterations: z <- tanh(c + z B^T) ----
    const int cg = tid & 15;       // column group (16 groups of 8 states)
    const int rg = tid >> 4;       // row group    (16 groups of 8 rows)
    const int r0 = rg * 8;
    const int c0 = cg * 8;

    for (int it = 0; it < NAPP - 1; ++it) {
        float acc[8][8];
        #pragma unroll
        for (int a = 0; a < 8; ++a)
            #pragma unroll
            for (int b = 0; b < 8; ++b) acc[a][b] = 0.0f;

        #pragma unroll 2
        for (int j = 0; j < D; ++j) {
            float4 za0 = *(const float4*)&ZT[j * LDZ + r0];
            float4 za1 = *(const float4*)&ZT[j * LDZ + r0 + 4];
            float4 wb0 = *(const float4*)&W [j * LDZ + c0];
            float4 wb1 = *(const float4*)&W [j * LDZ + c0 + 4];
            float za[8] = {za0.x, za0.y, za0.z, za0.w, za1.x, za1.y, za1.z, za1.w};
            float wb[8] = {wb0.x, wb0.y, wb0.z, wb0.w, wb1.x, wb1.y, wb1.z, wb1.w};
            #pragma unroll
            for (int a = 0; a < 8; ++a)
                #pragma unroll
                for (int b = 0; b < 8; ++b)
                    acc[a][b] += za[a] * wb[b];
        }
        __syncthreads();   // all GEMM reads of ZT complete before overwrite

        #pragma unroll
        for (int cc = 0; cc < 8; ++cc) {
            int i = c0 + cc;
            float4 cv0 = *(const float4*)&CT[i * LDZ + r0];
            float4 cv1 = *(const float4*)&CT[i * LDZ + r0 + 4];
            float4 z0, z1;
            z0.x = tanh_fast(cv0.x + acc[0][cc]);
            z0.y = tanh_fast(cv0.y + acc[1][cc]);
            z0.z = tanh_fast(cv0.z + acc[2][cc]);
            z0.w = tanh_fast(cv0.w + acc[3][cc]);
            z1.x = tanh_fast(cv1.x + acc[4][cc]);
            z1.y = tanh_fast(cv1.y + acc[5][cc]);
            z1.z = tanh_fast(cv1.z + acc[6][cc]);
            z1.w = tanh_fast(cv1.w + acc[7][cc]);
            *(float4*)&ZT[i * LDZ + r0]     = z0;
            *(float4*)&ZT[i * LDZ + r0 + 4] = z1;
        }
        __syncthreads();
    }

    // ---- y = z_star h^T + h_b ----
    if (tid < TM) {
        float acc = hb[0];
        #pragma unroll 8
        for (int i = 0; i < D; ++i)
            acc += hs[i] * ZT[i * LDZ + tid];
        out[row0 + tid] = acc;
    }
}

extern "C" void kernel_launch(void* const* d_in, const int* in_sizes, int n_in,
                              void* d_out, int out_size) {
    const float* x  = (const float*)d_in[0];
    const float* Aw = (const float*)d_in[1];
    const float* Ab = (const float*)d_in[2];
    const float* Bw = (const float*)d_in[3];
    const float* Bb = (const float*)d_in[4];
    const float* hw = (const float*)d_in[5];
    const float* hb = (const float*)d_in[6];
    float* out = (float*)d_out;

    int batch = in_sizes[0] / 4;       // x is [batch, 4]
    int grid  = batch / TM;            // 131072 / 128 = 1024

    cudaFuncSetAttribute(deq_kernel,
                         cudaFuncAttributeMaxDynamicSharedMemorySize,
                         SMEM_BYTES);
    deq_kernel<<<grid, THREADS, SMEM_BYTES>>>(x, Aw, Ab, Bw, Bb, hw, hb, out);
}

// round 2
// speedup vs baseline: 2.2054x; 2.2054x over previous
#include <cuda_runtime.h>
#include <cstdint>

// DEQ: z <- tanh(c + z B^T), 5 total tanh applications (contraction ~0.11/iter,
// truncation error ~6e-5 rel << 1e-3), then y = z h^T + h_b.
//
// One CTA = 128 batch rows resident in SMEM. fp32 GEMM with 8x8 register tiles
// using Blackwell packed fma.rn.f32x2 (2 FLOPs per fma-pipe issue slot).

#define D        128
#define TM       128
#define LDZ      132
#define ITERS    4        // tanh applications after z1 (total apps = 5)
#define THREADS  256

#define OFF_W    0
#define OFF_ZT   (D*LDZ)
#define OFF_CT   (2*D*LDZ)
#define OFF_HS   (3*D*LDZ)
#define OFF_AW   (OFF_HS + D)
#define OFF_AB   (OFF_AW + 4*D)
#define SMEM_FLOATS (OFF_AB + D)
#define SMEM_BYTES  (SMEM_FLOATS*4)

// Exact tanh (final application only): exp-identity, ~1e-7 abs accuracy.
__device__ __forceinline__ float tanh_exact(float v) {
    float e = __expf(2.0f * v);
    return 1.0f - __fdividef(2.0f, e + 1.0f);
}
// 1-MUFU tanh for intermediate applications (error damped x0.11 per later iter).
__device__ __forceinline__ float tanh_apx(float v) {
    float r;
    asm("tanh.approx.f32 %0, %1;" : "=f"(r) : "f"(v));
    return r;
}

__global__ void __launch_bounds__(THREADS, 1)
deq_kernel(const float* __restrict__ x,
           const float* __restrict__ Aw,
           const float* __restrict__ Ab,
           const float* __restrict__ Bw,
           const float* __restrict__ Bb,
           const float* __restrict__ hw,
           const float* __restrict__ hb,
           float* __restrict__ out)
{
    extern __shared__ float sm[];
    float* W  = sm + OFF_W;          // W[j*LDZ + i] = Bw[i*D + j]   (B^T)
    float* ZT = sm + OFF_ZT;         // ZT[i*LDZ + r] = z[r][i]
    float* CT = sm + OFF_CT;         // CT[i*LDZ + r] = c[r][i]
    float* hs = sm + OFF_HS;
    float* aw = sm + OFF_AW;
    float* ab = sm + OFF_AB;

    const int tid  = threadIdx.x;
    const int row0 = blockIdx.x * TM;
    const uint32_t sbase = (uint32_t)__cvta_generic_to_shared(sm);

    // ---- stage parameters ----
    for (int i = tid; i < D; i += THREADS) {
        hs[i] = hw[i];
        ab[i] = Ab[i] + Bb[i];
    }
    for (int i = tid; i < D * 4; i += THREADS) aw[i] = Aw[i];
    for (int idx = tid; idx < D * D; idx += THREADS) {
        int i = idx >> 7;
        int j = idx & (D - 1);
        W[j * LDZ + i] = Bw[idx];
    }
    __syncthreads();

    // ---- c = x A^T + (A_b + B_b), z1 = tanh(c) ----
    const float4* x4 = (const float4*)x;
    for (int idx = tid; idx < D * TM; idx += THREADS) {
        int i = idx >> 7;
        int r = idx & (TM - 1);
        float4 xv = x4[row0 + r];
        float c = ab[i]
                + xv.x * aw[i * 4 + 0]
                + xv.y * aw[i * 4 + 1]
                + xv.z * aw[i * 4 + 2]
                + xv.w * aw[i * 4 + 3];
        CT[i * LDZ + r] = c;
        ZT[i * LDZ + r] = tanh_apx(c);
    }
    __syncthreads();

    // ---- fixed-point iterations: z <- tanh(c + z B^T) ----
    const int cg = tid & 15;
    const int rg = tid >> 4;
    const int r0 = rg * 8;
    const int c0 = cg * 8;

    for (int it = 0; it < ITERS; ++it) {
        unsigned long long acc[4][8];   // acc[a2][b] = rows {r0+2a2, r0+2a2+1}, col c0+b
        #pragma unroll
        for (int a2 = 0; a2 < 4; ++a2)
            #pragma unroll
            for (int b = 0; b < 8; ++b) acc[a2][b] = 0ull;

        uint32_t za_a = sbase + 4u * (OFF_ZT + r0);
        uint32_t wb_a = sbase + 4u * (OFF_W  + c0);
        #pragma unroll 2
        for (int j = 0; j < D; ++j) {
            unsigned long long za[4];
            asm volatile("ld.shared.v2.b64 {%0,%1}, [%2];"
                         : "=l"(za[0]), "=l"(za[1]) : "r"(za_a));
            asm volatile("ld.shared.v2.b64 {%0,%1}, [%2];"
                         : "=l"(za[2]), "=l"(za[3]) : "r"(za_a + 16));
            uint32_t w[8];
            asm volatile("ld.shared.v4.b32 {%0,%1,%2,%3}, [%4];"
                         : "=r"(w[0]), "=r"(w[1]), "=r"(w[2]), "=r"(w[3]) : "r"(wb_a));
            asm volatile("ld.shared.v4.b32 {%0,%1,%2,%3}, [%4];"
                         : "=r"(w[4]), "=r"(w[5]), "=r"(w[6]), "=r"(w[7]) : "r"(wb_a + 16));
            #pragma unroll
            for (int b = 0; b < 8; ++b) {
                unsigned long long ws;
                asm("mov.b64 %0, {%1,%2};" : "=l"(ws) : "r"(w[b]), "r"(w[b]));
                #pragma unroll
                for (int a2 = 0; a2 < 4; ++a2)
                    asm("fma.rn.f32x2 %0, %1, %2, %0;"
                        : "+l"(acc[a2][b]) : "l"(za[a2]), "l"(ws));
            }
            za_a += 4 * LDZ;
            wb_a += 4 * LDZ;
        }
        __syncthreads();   // GEMM reads of ZT complete before overwrite

        const bool last = (it == ITERS - 1);
        #pragma unroll
        for (int b = 0; b < 8; ++b) {
            int i = c0 + b;
            float4 cv0 = *(const float4*)&CT[i * LDZ + r0];
            float4 cv1 = *(const float4*)&CT[i * LDZ + r0 + 4];
            float v[8];
            #pragma unroll
            for (int a2 = 0; a2 < 4; ++a2) {
                uint32_t lo, hi;
                asm("mov.b64 {%0,%1}, %2;" : "=r"(lo), "=r"(hi) : "l"(acc[a2][b]));
                v[2 * a2]     = __uint_as_float(lo);
                v[2 * a2 + 1] = __uint_as_float(hi);
            }
            float p[8] = {cv0.x + v[0], cv0.y + v[1], cv0.z + v[2], cv0.w + v[3],
                          cv1.x + v[4], cv1.y + v[5], cv1.z + v[6], cv1.w + v[7]};
            float z[8];
            if (last) {
                #pragma unroll
                for (int k = 0; k < 8; ++k) z[k] = tanh_exact(p[k]);
            } else {
                #pragma unroll
                for (int k = 0; k < 8; ++k) z[k] = tanh_apx(p[k]);
            }
            float4 z0 = {z[0], z[1], z[2], z[3]};
            float4 z1 = {z[4], z[5], z[6], z[7]};
            *(float4*)&ZT[i * LDZ + r0]     = z0;
            *(float4*)&ZT[i * LDZ + r0 + 4] = z1;
        }
        __syncthreads();
    }

    // ---- y = z_star h^T + h_b (2 threads per row, shfl combine) ----
    {
        int r  = tid >> 1;
        int h0 = (tid & 1) * 64;
        float acc = 0.0f;
        #pragma unroll 8
        for (int i = 0; i < 64; ++i)
            acc += hs[h0 + i] * ZT[(h0 + i) * LDZ + r];
        acc += __shfl_xor_sync(0xffffffffu, acc, 1);
        if ((tid & 1) == 0) out[row0 + r] = acc + hb[0];
    }
}

extern "C" void kernel_launch(void* const* d_in, const int* in_sizes, int n_in,
                              void* d_out, int out_size) {
    const float* x  = (const float*)d_in[0];
    const float* Aw = (const float*)d_in[1];
    const float* Ab = (const float*)d_in[2];
    const float* Bw = (const float*)d_in[3];
    const float* Bb = (const float*)d_in[4];
    const float* hw = (const float*)d_in[5];
    const float* hb = (const float*)d_in[6];
    float* out = (float*)d_out;

    int batch = in_sizes[0] / 4;   // x is [batch, 4]
    int grid  = batch / TM;        // 1024

    cudaFuncSetAttribute(deq_kernel,
                         cudaFuncAttributeMaxDynamicSharedMemorySize,
                         SMEM_BYTES);
    deq_kernel<<<grid, THREADS, SMEM_BYTES>>>(x, Aw, Ab, Bw, Bb, hw, hb, out);
}

// round 4
// speedup vs baseline: 3.0204x; 1.3696x over previous
#include <cuda_runtime.h>
#include <cuda_bf16.h>
#include <cstdint>

// DEQ via warp-level bf16 HMMA (mma.sync.m16n8k16): z <- tanh(c + z B^T),
// 5 tanh applications (z1 = tanh(c), then 4 GEMM iterations; last fuses y = z.h).
// One CTA = 128 batch rows, 8 warps, each warp owns a 16-row band with z kept
// in A-operand register fragments across iterations (acc layout == A layout).
// B (bf16) and c (fp32) in SMEM; no __syncthreads in the iteration loop.

#define THREADS 256
#define LDB_B   272        // bytes per B row (136 bf16: 128 + pad -> conflict-free LDSM)
#define LDC_F   132        // floats per c row (528 B: 128 + pad -> conflict-free LDS.64)
#define SM_B    0          // 128 * 272                = 34816 B
#define SM_C    34816      // 128 * 528                = 67584 B
#define SM_H    102400     // 128 f32                  =   512 B
#define SM_TOTAL 102912

__device__ __forceinline__ float tanh_exact(float v) {
    float e = __expf(2.0f * v);
    return 1.0f - __fdividef(2.0f, e + 1.0f);
}
__device__ __forceinline__ float tanh_apx(float v) {
    float r; asm("tanh.approx.f32 %0, %1;" : "=f"(r) : "f"(v)); return r;
}
// pack {lo, hi} floats into bf16x2 (first src operand -> high half)
__device__ __forceinline__ uint32_t packlh(float lo, float hi) {
    uint32_t r;
    asm("cvt.rn.satfinite.bf16x2.f32 %0, %1, %2;" : "=r"(r) : "f"(hi), "f"(lo));
    return r;
}
__device__ __forceinline__ void mma16816(float* d, const uint32_t* a,
                                         uint32_t b0, uint32_t b1) {
    asm volatile(
        "mma.sync.aligned.m16n8k16.row.col.f32.bf16.bf16.f32 "
        "{%0,%1,%2,%3}, {%4,%5,%6,%7}, {%8,%9}, {%0,%1,%2,%3};"
        : "+f"(d[0]), "+f"(d[1]), "+f"(d[2]), "+f"(d[3])
        : "r"(a[0]), "r"(a[1]), "r"(a[2]), "r"(a[3]), "r"(b0), "r"(b1));
}
__device__ __forceinline__ void ldsm4(uint32_t* r, uint32_t addr) {
    asm volatile("ldmatrix.sync.aligned.m8n8.x4.shared.b16 {%0,%1,%2,%3}, [%4];"
                 : "=r"(r[0]), "=r"(r[1]), "=r"(r[2]), "=r"(r[3]) : "r"(addr));
}

// One GEMM iteration: out = z_cur * B^T; z_next = tanh(c + out)  (or y-reduce on LAST)
template<bool LAST>
__device__ __forceinline__ void gemm_iter(
    uint32_t bb,                 // per-thread LDSM base address (shared space)
    const float2* c2w,           // c pairs, this thread's row (qr)
    const float2* c2w8,          // c pairs, row qr+8
    const float2* h2,            // h weights as pairs
    const uint32_t A[8][4], uint32_t An[8][4],
    float& y0, float& y1, int qc)
{
    #pragma unroll
    for (int ntp = 0; ntp < 8; ++ntp) {
        uint32_t b0[16], b1[16];
        #pragma unroll
        for (int l = 0; l < 4; ++l) {
            ldsm4(&b0[4 * l], bb + (uint32_t)(2 * ntp)     * (8 * LDB_B) + l * 64);
            ldsm4(&b1[4 * l], bb + (uint32_t)(2 * ntp + 1) * (8 * LDB_B) + l * 64);
        }
        float acc0[4] = {0.f, 0.f, 0.f, 0.f};
        float acc1[4] = {0.f, 0.f, 0.f, 0.f};
        #pragma unroll
        for (int kt = 0; kt < 8; ++kt) {
            mma16816(acc0, A[kt], b0[2 * kt], b0[2 * kt + 1]);
            mma16816(acc1, A[kt], b1[2 * kt], b1[2 * kt + 1]);
        }
        #pragma unroll
        for (int h = 0; h < 2; ++h) {
            const int nt = 2 * ntp + h;
            const float* acc = h ? acc1 : acc0;
            float2 cl0 = c2w [4 * nt + qc];
            float2 cl1 = c2w8[4 * nt + qc];
            float p0 = acc[0] + cl0.x, p1 = acc[1] + cl0.y;
            float p2 = acc[2] + cl1.x, p3 = acc[3] + cl1.y;
            if (LAST) {
                float2 hv = h2[4 * nt + qc];
                y0 += hv.x * tanh_exact(p0) + hv.y * tanh_exact(p1);
                y1 += hv.x * tanh_exact(p2) + hv.y * tanh_exact(p3);
            } else {
                An[ntp][2 * h + 0] = packlh(tanh_apx(p0), tanh_apx(p1));
                An[ntp][2 * h + 1] = packlh(tanh_apx(p2), tanh_apx(p3));
            }
        }
    }
}

__global__ void __launch_bounds__(THREADS, 2)
deq_mma_kernel(const float* __restrict__ x,
               const float* __restrict__ Aw,
               const float* __restrict__ Ab,
               const float* __restrict__ Bw,
               const float* __restrict__ Bb,
               const float* __restrict__ hw,
               const float* __restrict__ hb,
               float* __restrict__ out)
{
    extern __shared__ char smem[];
    const int tid  = threadIdx.x;
    const int row0 = blockIdx.x * 128;

    // ---- stage B as bf16, padded rows (row = n-index i, col = k-index j) ----
    #pragma unroll 4
    for (int idx = tid; idx < 128 * 128; idx += THREADS) {
        int i = idx >> 7, j = idx & 127;
        *(__nv_bfloat16*)(smem + SM_B + i * LDB_B + j * 2) = __float2bfloat16(Bw[idx]);
    }
    if (tid < 128) ((float*)(smem + SM_H))[tid] = hw[tid];

    // ---- c = x A^T + (A_b + B_b)  (thread = half row) ----
    {
        int r  = tid >> 1;
        int i0 = (tid & 1) << 6;
        float4 xv = ((const float4*)x)[row0 + r];
        float* crow = (float*)(smem + SM_C) + r * LDC_F;
        #pragma unroll 8
        for (int k = 0; k < 64; ++k) {
            int i = i0 + k;
            float4 a = ((const float4*)Aw)[i];
            crow[i] = Ab[i] + Bb[i]
                    + xv.x * a.x + xv.y * a.y + xv.z * a.z + xv.w * a.w;
        }
    }
    __syncthreads();

    // ---- per-warp fragment setup ----
    const int lane = tid & 31, wid = tid >> 5;
    const int qr = lane >> 2, qc = lane & 3;
    const int rb = wid * 16;
    const float2* c2  = (const float2*)(smem + SM_C);
    const float2* c2w  = c2 + (rb + qr) * (LDC_F / 2);
    const float2* c2w8 = c2w + 8 * (LDC_F / 2);
    const float2* h2  = (const float2*)(smem + SM_H);
    const uint32_t sb = (uint32_t)__cvta_generic_to_shared(smem);
    const uint32_t bb = sb + SM_B + (uint32_t)(lane & 7) * LDB_B + (uint32_t)(lane >> 3) * 16;

    // ---- z1 = tanh(c) into A fragments ----
    uint32_t A[8][4], An[8][4];
    #pragma unroll
    for (int kt = 0; kt < 8; ++kt) {
        float2 u0 = c2w [8 * kt + qc];
        float2 u1 = c2w8[8 * kt + qc];
        float2 u2 = c2w [8 * kt + 4 + qc];
        float2 u3 = c2w8[8 * kt + 4 + qc];
        A[kt][0] = packlh(tanh_apx(u0.x), tanh_apx(u0.y));
        A[kt][1] = packlh(tanh_apx(u1.x), tanh_apx(u1.y));
        A[kt][2] = packlh(tanh_apx(u2.x), tanh_apx(u2.y));
        A[kt][3] = packlh(tanh_apx(u3.x), tanh_apx(u3.y));
    }

    // ---- 4 GEMM iterations (z2..z5), last fuses y = z5 . h ----
    float y0 = 0.f, y1 = 0.f;
    gemm_iter<false>(bb, c2w, c2w8, h2, A,  An, y0, y1, qc);
    gemm_iter<false>(bb, c2w, c2w8, h2, An, A,  y0, y1, qc);
    gemm_iter<false>(bb, c2w, c2w8, h2, A,  An, y0, y1, qc);
    gemm_iter<true >(bb, c2w, c2w8, h2, An, A,  y0, y1, qc);

    // ---- reduce y across the 4 lanes sharing a row, write out ----
    y0 += __shfl_xor_sync(0xffffffffu, y0, 1);
    y0 += __shfl_xor_sync(0xffffffffu, y0, 2);
    y1 += __shfl_xor_sync(0xffffffffu, y1, 1);
    y1 += __shfl_xor_sync(0xffffffffu, y1, 2);
    if (qc == 0) {
        float hb0 = hb[0];
        out[row0 + rb + qr]     = y0 + hb0;
        out[row0 + rb + qr + 8] = y1 + hb0;
    }
}

extern "C" void kernel_launch(void* const* d_in, const int* in_sizes, int n_in,
                              void* d_out, int out_size) {
    const float* x  = (const float*)d_in[0];
    const float* Aw = (const float*)d_in[1];
    const float* Ab = (const float*)d_in[2];
    const float* Bw = (const float*)d_in[3];
    const float* Bb = (const float*)d_in[4];
    const float* hw = (const float*)d_in[5];
    const float* hb = (const float*)d_in[6];
    float* out = (float*)d_out;

    int batch = in_sizes[0] / 4;     // x is [batch, 4]
    int grid  = batch / 128;         // 1024

    cudaFuncSetAttribute(deq_mma_kernel,
                         cudaFuncAttributeMaxDynamicSharedMemorySize,
                         SM_TOTAL);
    deq_mma_kernel<<<grid, THREADS, SM_TOTAL>>>(x, Aw, Ab, Bw, Bb, hw, hb, out);
}